// round 2
// baseline (speedup 1.0000x reference)
#include <cuda_runtime.h>
#include <cuda_bf16.h>

// Problem constants
#define B_   512
#define S_   64
#define K_   8
#define D_   16
#define NSTEPS_ 100
#define NUNITS_ 128

#define FULL 0xffffffffu

__device__ __forceinline__ float sigmoidf_(float x) {
    return 1.0f / (1.0f + __expf(-x));
}

// ---------------------------------------------------------------------------
// Kernel A: diffusion MLP branch. 8 batch rows per block, 128 threads.
// out[b*17 + 1 + d] = diff_out[b][d]
// ---------------------------------------------------------------------------
__global__ __launch_bounds__(128) void diff_kernel(
    const float* __restrict__ usr_emb, const float* __restrict__ noise,
    const int* __restrict__ u, const int* __restrict__ t,
    const float* __restrict__ W1, const float* __restrict__ b1,
    const float* __restrict__ W2, const float* __restrict__ b2,
    const float* __restrict__ W3, const float* __restrict__ b3,
    const float* __restrict__ W4, const float* __restrict__ b4,
    const float* __restrict__ se1, const float* __restrict__ se2,
    const float* __restrict__ se3,
    float* __restrict__ out)
{
    __shared__ float xs[8][16];
    __shared__ float bufA[8][128];
    __shared__ float bufB[8][128];
    __shared__ float sa[8], so[8];
    __shared__ int   tt[8];

    const int tid = threadIdx.x;
    const int blk = blockIdx.x;

    if (tid < 8) {
        int b  = blk * 8 + tid;
        int tv = t[b];
        tt[tid] = tv;
        float prod = 1.0f;
        for (int i = 0; i <= tv; i++) {
            float z    = -6.0f + 12.0f * (float)i / 99.0f;
            float sig  = 1.0f / (1.0f + __expf(-z));
            float beta = sig * (0.005f - 1e-5f) + 1e-5f;
            prod *= (1.0f - beta);
        }
        sa[tid] = sqrtf(prod);
        so[tid] = sqrtf(1.0f - prod);
    }
    __syncthreads();

    {
        int bb = tid >> 4, d = tid & 15;
        int b = blk * 8 + bb;
        xs[bb][d] = usr_emb[u[b] * D_ + d] * sa[bb] + noise[b * D_ + d] * so[bb];
    }
    __syncthreads();

    float acc[8];

    // layer 1: 16 -> 128
    #pragma unroll
    for (int bb = 0; bb < 8; bb++) acc[bb] = b1[tid];
    #pragma unroll
    for (int i = 0; i < 16; i++) {
        float w = W1[i * 128 + tid];
        #pragma unroll
        for (int bb = 0; bb < 8; bb++) acc[bb] += xs[bb][i] * w;
    }
    #pragma unroll
    for (int bb = 0; bb < 8; bb++)
        bufA[bb][tid] = fmaxf(acc[bb] + se1[tt[bb] * 128 + tid], 0.0f);
    __syncthreads();

    // layer 2: 128 -> 128
    #pragma unroll
    for (int bb = 0; bb < 8; bb++) acc[bb] = b2[tid];
    for (int i = 0; i < 128; i++) {
        float w = W2[i * 128 + tid];
        #pragma unroll
        for (int bb = 0; bb < 8; bb++) acc[bb] += bufA[bb][i] * w;
    }
    #pragma unroll
    for (int bb = 0; bb < 8; bb++)
        bufB[bb][tid] = fmaxf(acc[bb] + se2[tt[bb] * 128 + tid], 0.0f);
    __syncthreads();

    // layer 3: 128 -> 128
    #pragma unroll
    for (int bb = 0; bb < 8; bb++) acc[bb] = b3[tid];
    for (int i = 0; i < 128; i++) {
        float w = W3[i * 128 + tid];
        #pragma unroll
        for (int bb = 0; bb < 8; bb++) acc[bb] += bufB[bb][i] * w;
    }
    #pragma unroll
    for (int bb = 0; bb < 8; bb++)
        bufA[bb][tid] = fmaxf(acc[bb] + se3[tt[bb] * 128 + tid], 0.0f);
    __syncthreads();

    // layer 4: 128 -> 16 (no activation)
    {
        int bb = tid >> 4, d = tid & 15;
        float o = b4[d];
        for (int i = 0; i < 128; i++)
            o += bufA[bb][i] * W4[i * 16 + d];
        out[(blk * 8 + bb) * 17 + 1 + d] = o;
    }
}

// ---------------------------------------------------------------------------
// Kernel B: KGCN aggregation + pooling + FC head. One block per batch element.
// 512 threads = 16 warps; each warp handles 4 sequence positions.
// Lane layout: lane = j*4 + q, j = neighbor index (0..7), q = float4 chunk (0..3).
// ---------------------------------------------------------------------------
__global__ __launch_bounds__(512) void kgcn_kernel(
    const float* __restrict__ ent_emb, const float* __restrict__ rel_emb,
    const float* __restrict__ usr_emb,
    const float* __restrict__ agg_W, const float* __restrict__ agg_b,
    const float* __restrict__ fc1_W, const float* __restrict__ fc1_b,
    const float* __restrict__ fc2_W, const float* __restrict__ fc2_b,
    const int* __restrict__ u, const int* __restrict__ v,
    const int* __restrict__ click_seq,
    const int* __restrict__ adj_ent, const int* __restrict__ adj_rel,
    float* __restrict__ out)
{
    __shared__ float4 s_user4[4];
    __shared__ float4 s_rel4[64 * 4];
    __shared__ float  s_W[256];
    __shared__ float  s_b[16];
    __shared__ float4 s_in4[16][4];
    __shared__ float4 s_h04[16][4];
    __shared__ float4 s_h14[16][8][4];
    __shared__ float  s_sumred[16][16];
    __shared__ float  s_maxred[16][16];
    __shared__ float  s_fusion[32];
    __shared__ float  s_fc[64];
    __shared__ float  s_dot[16];

    const int b   = blockIdx.x;
    const int tid = threadIdx.x;
    const int wid = tid >> 5;
    const int lane = tid & 31;
    const int j = lane >> 2;
    const int q = lane & 3;

    // stage user vector, full rel_emb table, aggregator weights
    if (tid < 16) ((float*)s_user4)[tid] = usr_emb[u[b] * D_ + tid];
    for (int i = tid; i < 64 * 16; i += 512) ((float*)s_rel4)[i] = rel_emb[i];
    if (tid < 256) s_W[tid] = agg_W[tid];
    if (tid >= 256 && tid < 272) s_b[tid - 256] = agg_b[tid - 256];
    __syncthreads();

    const float4* ent4 = reinterpret_cast<const float4*>(ent_emb);
    const float4  u4 = s_user4[q];

    float acc_sum = 0.0f, acc_max = 0.0f;   // valid on lanes < 16 (d = lane)

    for (int it = 0; it < 4; ++it) {
        const int s  = wid * 4 + it;
        const int e0 = click_seq[b * S_ + s];
        const int e1j = adj_ent[e0 * K_ + j];
        const int r0j = adj_rel[e0 * K_ + j];

        // hop-0 score (reused in both iterations)
        float4 rr0 = s_rel4[r0j * 4 + q];
        float sc0 = u4.x * rr0.x + u4.y * rr0.y + u4.z * rr0.z + u4.w * rr0.w;
        sc0 += __shfl_xor_sync(FULL, sc0, 1);
        sc0 += __shfl_xor_sync(FULL, sc0, 2);
        sc0 *= 0.0625f;
        float m0 = sc0;
        m0 = fmaxf(m0, __shfl_xor_sync(FULL, m0, 4));
        m0 = fmaxf(m0, __shfl_xor_sync(FULL, m0, 8));
        m0 = fmaxf(m0, __shfl_xor_sync(FULL, m0, 16));
        float ex0 = __expf(sc0 - m0);
        float sm0 = ex0;
        sm0 += __shfl_xor_sync(FULL, sm0, 4);
        sm0 += __shfl_xor_sync(FULL, sm0, 8);
        sm0 += __shfl_xor_sync(FULL, sm0, 16);
        const float p0 = ex0 / sm0;

        const float4 v1    = ent4[e1j * 4 + q];   // ev1[j], chunk q
        const float4 self0 = ent4[e0 * 4 + q];    // ev0, chunk q

        // --- iter 0, hop 1: 8 groups k, neighbors over j ---
        #pragma unroll 1
        for (int k = 0; k < 8; k++) {
            const int e1k = __shfl_sync(FULL, e1j, k * 4);
            const int r1  = adj_rel[e1k * K_ + j];
            const int e2  = adj_ent[e1k * K_ + j];

            float4 rr = s_rel4[r1 * 4 + q];
            float sc = u4.x * rr.x + u4.y * rr.y + u4.z * rr.z + u4.w * rr.w;
            sc += __shfl_xor_sync(FULL, sc, 1);
            sc += __shfl_xor_sync(FULL, sc, 2);
            sc *= 0.0625f;
            float m = sc;
            m = fmaxf(m, __shfl_xor_sync(FULL, m, 4));
            m = fmaxf(m, __shfl_xor_sync(FULL, m, 8));
            m = fmaxf(m, __shfl_xor_sync(FULL, m, 16));
            float ex = __expf(sc - m);
            float sm = ex;
            sm += __shfl_xor_sync(FULL, sm, 4);
            sm += __shfl_xor_sync(FULL, sm, 8);
            sm += __shfl_xor_sync(FULL, sm, 16);
            const float p = ex / sm;

            float4 nv = ent4[e2 * 4 + q];
            float ax = p * nv.x, ay = p * nv.y, az = p * nv.z, aw = p * nv.w;
            ax += __shfl_xor_sync(FULL, ax, 4);  ay += __shfl_xor_sync(FULL, ay, 4);
            az += __shfl_xor_sync(FULL, az, 4);  aw += __shfl_xor_sync(FULL, aw, 4);
            ax += __shfl_xor_sync(FULL, ax, 8);  ay += __shfl_xor_sync(FULL, ay, 8);
            az += __shfl_xor_sync(FULL, az, 8);  aw += __shfl_xor_sync(FULL, aw, 8);
            ax += __shfl_xor_sync(FULL, ax, 16); ay += __shfl_xor_sync(FULL, ay, 16);
            az += __shfl_xor_sync(FULL, az, 16); aw += __shfl_xor_sync(FULL, aw, 16);

            // self = ev1[k] chunk q: grab from the lane holding (j=k, q)
            const int src = k * 4 + q;
            float skx = __shfl_sync(FULL, v1.x, src);
            float sky = __shfl_sync(FULL, v1.y, src);
            float skz = __shfl_sync(FULL, v1.z, src);
            float skw = __shfl_sync(FULL, v1.w, src);

            if (j == 0)
                s_in4[wid][q] = make_float4(skx + ax, sky + ay, skz + az, skw + aw);
            __syncwarp();
            if (lane < 16) {
                const float* sin = (const float*)s_in4[wid];
                float o = s_b[lane];
                #pragma unroll
                for (int i = 0; i < 16; i++) o += sin[i] * s_W[i * 16 + lane];
                o = sigmoidf_(o);
                ((float*)s_h14[wid][k])[lane] = o;
            }
            __syncwarp();
        }

        // --- iter 0, hop 0 ---
        {
            float ax = p0 * v1.x, ay = p0 * v1.y, az = p0 * v1.z, aw = p0 * v1.w;
            ax += __shfl_xor_sync(FULL, ax, 4);  ay += __shfl_xor_sync(FULL, ay, 4);
            az += __shfl_xor_sync(FULL, az, 4);  aw += __shfl_xor_sync(FULL, aw, 4);
            ax += __shfl_xor_sync(FULL, ax, 8);  ay += __shfl_xor_sync(FULL, ay, 8);
            az += __shfl_xor_sync(FULL, az, 8);  aw += __shfl_xor_sync(FULL, aw, 8);
            ax += __shfl_xor_sync(FULL, ax, 16); ay += __shfl_xor_sync(FULL, ay, 16);
            az += __shfl_xor_sync(FULL, az, 16); aw += __shfl_xor_sync(FULL, aw, 16);
            if (j == 0)
                s_in4[wid][q] = make_float4(self0.x + ax, self0.y + ay,
                                            self0.z + az, self0.w + aw);
            __syncwarp();
            if (lane < 16) {
                const float* sin = (const float*)s_in4[wid];
                float o = s_b[lane];
                #pragma unroll
                for (int i = 0; i < 16; i++) o += sin[i] * s_W[i * 16 + lane];
                o = sigmoidf_(o);
                ((float*)s_h04[wid])[lane] = o;
            }
            __syncwarp();
        }

        // --- iter 1, hop 0: neighbors are h1[k], softmax weights p0 reused ---
        {
            float4 hv = s_h14[wid][j][q];
            float ax = p0 * hv.x, ay = p0 * hv.y, az = p0 * hv.z, aw = p0 * hv.w;
            ax += __shfl_xor_sync(FULL, ax, 4);  ay += __shfl_xor_sync(FULL, ay, 4);
            az += __shfl_xor_sync(FULL, az, 4);  aw += __shfl_xor_sync(FULL, aw, 4);
            ax += __shfl_xor_sync(FULL, ax, 8);  ay += __shfl_xor_sync(FULL, ay, 8);
            az += __shfl_xor_sync(FULL, az, 8);  aw += __shfl_xor_sync(FULL, aw, 8);
            ax += __shfl_xor_sync(FULL, ax, 16); ay += __shfl_xor_sync(FULL, ay, 16);
            az += __shfl_xor_sync(FULL, az, 16); aw += __shfl_xor_sync(FULL, aw, 16);
            float4 h0q = s_h04[wid][q];
            if (j == 0)
                s_in4[wid][q] = make_float4(h0q.x + ax, h0q.y + ay,
                                            h0q.z + az, h0q.w + aw);
            __syncwarp();
            if (lane < 16) {
                const float* sin = (const float*)s_in4[wid];
                float o = s_b[lane];
                #pragma unroll
                for (int i = 0; i < 16; i++) o += sin[i] * s_W[i * 16 + lane];
                o = tanhf(o);
                o = fmaxf(o, 0.0f);       // item = relu(out); >= 0
                acc_sum += o;
                acc_max = fmaxf(acc_max, o);
            }
            __syncwarp();
        }
    }

    if (lane < 16) {
        s_sumred[wid][lane] = acc_sum;
        s_maxred[wid][lane] = acc_max;
    }
    __syncthreads();

    // pooling across warps -> fusion[32]
    if (tid < 16) {
        float ssum = 0.0f, smax = 0.0f;
        #pragma unroll
        for (int w = 0; w < 16; w++) {
            ssum += s_sumred[w][tid];
            smax = fmaxf(smax, s_maxred[w][tid]);
        }
        s_fusion[tid]      = ssum;   // relu no-op: nonneg
        s_fusion[16 + tid] = smax;
    }
    __syncthreads();

    // fc1: 32 -> 64, relu
    if (tid < 64) {
        float o = fc1_b[tid];
        #pragma unroll
        for (int i = 0; i < 32; i++) o += s_fusion[i] * fc1_W[i * 64 + tid];
        s_fc[tid] = fmaxf(o, 0.0f);
    }
    __syncthreads();

    // fc2: 64 -> 16, relu; multiply with ent_emb[v[b]]
    if (tid < 16) {
        float o = fc2_b[tid];
        #pragma unroll
        for (int i = 0; i < 64; i++) o += s_fc[i] * fc2_W[i * 16 + tid];
        o = fmaxf(o, 0.0f);
        s_dot[tid] = o * ent_emb[v[b] * D_ + tid];
    }
    __syncthreads();

    if (tid == 0) {
        float d = 0.0f;
        #pragma unroll
        for (int i = 0; i < 16; i++) d += s_dot[i];
        out[b * 17] = sigmoidf_(d);
    }
}

// ---------------------------------------------------------------------------
// Input order (metadata.txt):
//  0 usr_emb  1 ent_emb  2 rel_emb  3 agg_W  4 agg_b
//  5 fc1_W    6 fc1_b    7 fc2_W    8 fc2_b
//  9 mlp_W1  10 mlp_b1  11 mlp_W2  12 mlp_b2 13 mlp_W3 14 mlp_b3
// 15 mlp_W4  16 mlp_b4  17 step_emb1 18 step_emb2 19 step_emb3
// 20 noise_e 21 u 22 v 23 click_seq 24 adj_ent 25 adj_rel 26 t
// ---------------------------------------------------------------------------
extern "C" void kernel_launch(void* const* d_in, const int* in_sizes, int n_in,
                              void* d_out, int out_size) {
    const float* usr_emb = (const float*)d_in[0];
    const float* ent_emb = (const float*)d_in[1];
    const float* rel_emb = (const float*)d_in[2];
    const float* agg_W   = (const float*)d_in[3];
    const float* agg_b   = (const float*)d_in[4];
    const float* fc1_W   = (const float*)d_in[5];
    const float* fc1_b   = (const float*)d_in[6];
    const float* fc2_W   = (const float*)d_in[7];
    const float* fc2_b   = (const float*)d_in[8];
    const float* mlp_W1  = (const float*)d_in[9];
    const float* mlp_b1  = (const float*)d_in[10];
    const float* mlp_W2  = (const float*)d_in[11];
    const float* mlp_b2  = (const float*)d_in[12];
    const float* mlp_W3  = (const float*)d_in[13];
    const float* mlp_b3  = (const float*)d_in[14];
    const float* mlp_W4  = (const float*)d_in[15];
    const float* mlp_b4  = (const float*)d_in[16];
    const float* se1     = (const float*)d_in[17];
    const float* se2     = (const float*)d_in[18];
    const float* se3     = (const float*)d_in[19];
    const float* noise_e = (const float*)d_in[20];
    const int*   u       = (const int*)d_in[21];
    const int*   v       = (const int*)d_in[22];
    const int*   click   = (const int*)d_in[23];
    const int*   adj_ent = (const int*)d_in[24];
    const int*   adj_rel = (const int*)d_in[25];
    const int*   t       = (const int*)d_in[26];
    float* out = (float*)d_out;

    diff_kernel<<<B_ / 8, 128>>>(usr_emb, noise_e, u, t,
                                 mlp_W1, mlp_b1, mlp_W2, mlp_b2,
                                 mlp_W3, mlp_b3, mlp_W4, mlp_b4,
                                 se1, se2, se3, out);

    kgcn_kernel<<<B_, 512>>>(ent_emb, rel_emb, usr_emb,
                             agg_W, agg_b, fc1_W, fc1_b, fc2_W, fc2_b,
                             u, v, click, adj_ent, adj_rel, out);
}

// round 3
// speedup vs baseline: 1.5122x; 1.5122x over previous
#include <cuda_runtime.h>
#include <cuda_bf16.h>

#define B_   512
#define S_   64
#define K_   8
#define D_   16
#define NSTEPS_ 100

#define FULL 0xffffffffu

__device__ __forceinline__ float sigmoidf_(float x) {
    return 1.0f / (1.0f + __expf(-x));
}

// alpha schedule table (filled by alpha_kernel each launch; deterministic)
__device__ float g_sa[NSTEPS_];
__device__ float g_so[NSTEPS_];

// ---------------------------------------------------------------------------
// Kernel 0: alpha schedule. sqrt(cumprod(1-beta)) and sqrt(1-cumprod).
// ---------------------------------------------------------------------------
__global__ void alpha_kernel() {
    __shared__ float bet[NSTEPS_];
    int tid = threadIdx.x;
    if (tid < NSTEPS_) {
        float z = -6.0f + 12.0f * (float)tid / 99.0f;
        float sig = 1.0f / (1.0f + __expf(-z));
        bet[tid] = sig * (0.005f - 1e-5f) + 1e-5f;
    }
    __syncthreads();
    if (tid == 0) {
        float prod = 1.0f;
        for (int i = 0; i < NSTEPS_; i++) {
            prod *= (1.0f - bet[i]);
            g_sa[i] = sqrtf(prod);
            g_so[i] = sqrtf(1.0f - prod);
        }
    }
}

// ---------------------------------------------------------------------------
// Kernel A: diffusion MLP. 2 batch rows per block, 256 blocks, 128 threads.
// ---------------------------------------------------------------------------
__global__ __launch_bounds__(128) void diff_kernel(
    const float* __restrict__ usr_emb, const float* __restrict__ noise,
    const int* __restrict__ u, const int* __restrict__ t,
    const float* __restrict__ W1, const float* __restrict__ b1,
    const float* __restrict__ W2, const float* __restrict__ b2,
    const float* __restrict__ W3, const float* __restrict__ b3,
    const float* __restrict__ W4, const float* __restrict__ b4,
    const float* __restrict__ se1, const float* __restrict__ se2,
    const float* __restrict__ se3,
    float* __restrict__ out)
{
    __shared__ float xs[2][16];
    __shared__ float bufA[2][128];
    __shared__ float bufB[2][128];

    const int tid = threadIdx.x;
    const int b0  = blockIdx.x * 2;
    const int t0  = t[b0];
    const int t1  = t[b0 + 1];

    if (tid < 32) {
        int r = tid >> 4, d = tid & 15;
        int b = b0 + r;
        int tv = r ? t1 : t0;
        xs[r][d] = usr_emb[u[b] * D_ + d] * g_sa[tv] + noise[b * D_ + d] * g_so[tv];
    }
    __syncthreads();

    float a0, a1;

    // layer 1: 16 -> 128
    a0 = b1[tid]; a1 = a0;
    #pragma unroll
    for (int i = 0; i < 16; i++) {
        float w = W1[i * 128 + tid];
        a0 += xs[0][i] * w;
        a1 += xs[1][i] * w;
    }
    bufA[0][tid] = fmaxf(a0 + se1[t0 * 128 + tid], 0.0f);
    bufA[1][tid] = fmaxf(a1 + se1[t1 * 128 + tid], 0.0f);
    __syncthreads();

    // layer 2: 128 -> 128
    a0 = b2[tid]; a1 = a0;
    #pragma unroll 8
    for (int i = 0; i < 128; i++) {
        float w = W2[i * 128 + tid];
        a0 += bufA[0][i] * w;
        a1 += bufA[1][i] * w;
    }
    bufB[0][tid] = fmaxf(a0 + se2[t0 * 128 + tid], 0.0f);
    bufB[1][tid] = fmaxf(a1 + se2[t1 * 128 + tid], 0.0f);
    __syncthreads();

    // layer 3: 128 -> 128
    a0 = b3[tid]; a1 = a0;
    #pragma unroll 8
    for (int i = 0; i < 128; i++) {
        float w = W3[i * 128 + tid];
        a0 += bufB[0][i] * w;
        a1 += bufB[1][i] * w;
    }
    bufA[0][tid] = fmaxf(a0 + se3[t0 * 128 + tid], 0.0f);
    bufA[1][tid] = fmaxf(a1 + se3[t1 * 128 + tid], 0.0f);
    __syncthreads();

    // layer 4: 128 -> 16
    if (tid < 32) {
        int r = tid >> 4, d = tid & 15;
        float o = b4[d];
        #pragma unroll 8
        for (int i = 0; i < 128; i++)
            o += bufA[r][i] * W4[i * 16 + d];
        out[(b0 + r) * 17 + 1 + d] = o;
    }
}

// ---------------------------------------------------------------------------
// Kernel B: KGCN. One block per batch element, 512 threads = 16 warps.
// Lane layout: g = lane>>2 (hop-1 group 0..7), q = lane&3 (float4 chunk).
// Softmax weights come from a per-block precomputed table
// E[r] = exp(user.rel[r]/16 - M); p_k = E[r_k] / sum_j E[r_j].
// ---------------------------------------------------------------------------
#define PITCH4 5   // float4 pitch per group (avoids LDS bank conflicts)

__global__ __launch_bounds__(512) void kgcn_kernel(
    const float* __restrict__ ent_emb, const float* __restrict__ rel_emb,
    const float* __restrict__ usr_emb,
    const float* __restrict__ agg_W, const float* __restrict__ agg_b,
    const float* __restrict__ fc1_W, const float* __restrict__ fc1_b,
    const float* __restrict__ fc2_W, const float* __restrict__ fc2_b,
    const int* __restrict__ u, const int* __restrict__ v,
    const int* __restrict__ click_seq,
    const int* __restrict__ adj_ent, const int* __restrict__ adj_rel,
    float* __restrict__ out)
{
    __shared__ float  s_user[16];
    __shared__ float  s_E[64];           // exp(score - M)
    __shared__ float  s_W[256];          // agg_W row-major [i][d]
    __shared__ float4 s_b4[4];
    __shared__ float4 s_in1[16][8 * PITCH4];  // hop-1 matvec inputs per warp
    __shared__ float4 s_in0[16][4];           // hop-0 matvec input per warp
    __shared__ float4 s_psum[16][4];
    __shared__ float4 s_pmax[16][4];
    __shared__ float  s_fusion[32];
    __shared__ float  s_fc[64];
    __shared__ float  s_dot[16];

    const int b    = blockIdx.x;
    const int tid  = threadIdx.x;
    const int wid  = tid >> 5;
    const int lane = tid & 31;
    const int g    = lane >> 2;
    const int q    = lane & 3;

    // ---- block preamble: user vec, E table, agg weights ----
    if (tid < 16) s_user[tid] = usr_emb[u[b] * D_ + tid];
    if (tid >= 32 && tid < 288) s_W[tid - 32] = agg_W[tid - 32];
    if (tid >= 288 && tid < 292) {
        int c = tid - 288;
        s_b4[c] = make_float4(agg_b[c * 4], agg_b[c * 4 + 1],
                              agg_b[c * 4 + 2], agg_b[c * 4 + 3]);
    }
    __syncthreads();

    if (tid < 64) {
        float sc = 0.0f;
        #pragma unroll
        for (int i = 0; i < 16; i++) sc += s_user[i] * rel_emb[tid * 16 + i];
        s_E[tid] = sc * 0.0625f;
    }
    __syncthreads();
    float mysc = 0.0f, mx = -1e30f;
    if (tid < 64) {
        mysc = s_E[tid];
        #pragma unroll 8
        for (int i = 0; i < 64; i++) mx = fmaxf(mx, s_E[i]);
    }
    __syncthreads();
    if (tid < 64) s_E[tid] = __expf(mysc - mx);
    __syncthreads();

    const float4* ent4 = reinterpret_cast<const float4*>(ent_emb);
    const int4*   adjE4 = reinterpret_cast<const int4*>(adj_ent);
    const int4*   adjR4 = reinterpret_cast<const int4*>(adj_rel);

    float4 acc_sum = make_float4(0.f, 0.f, 0.f, 0.f);
    float4 acc_max = make_float4(0.f, 0.f, 0.f, 0.f);

    for (int it = 0; it < 4; ++it) {
        const int s  = wid * 4 + it;
        const int e0 = click_seq[b * S_ + s];

        // this lane's hop-0 neighbor (group g) and its relation
        const int e1g = adj_ent[e0 * K_ + g];
        const int r0g = adj_rel[e0 * K_ + g];

        // hop-1 adjacency rows for group g (8 ints each, via 2x int4)
        const int4 eb0 = adjE4[e1g * 2];
        const int4 eb1 = adjE4[e1g * 2 + 1];
        const int4 rb0 = adjR4[e1g * 2];
        const int4 rb1 = adjR4[e1g * 2 + 1];

        // self rows
        const float4 e0row = ent4[e0 * 4 + q];
        const float4 v1    = ent4[e1g * 4 + q];

        // gather all 8 hop-2 neighbor chunks (MLP=8)
        int ei[8] = {eb0.x, eb0.y, eb0.z, eb0.w, eb1.x, eb1.y, eb1.z, eb1.w};
        float4 nv[8];
        #pragma unroll
        for (int j = 0; j < 8; j++) nv[j] = ent4[ei[j] * 4 + q];

        // softmax weights for group g from E table
        float pw[8];
        pw[0] = s_E[rb0.x]; pw[1] = s_E[rb0.y]; pw[2] = s_E[rb0.z]; pw[3] = s_E[rb0.w];
        pw[4] = s_E[rb1.x]; pw[5] = s_E[rb1.y]; pw[6] = s_E[rb1.z]; pw[7] = s_E[rb1.w];
        float inv1 = 1.0f / (pw[0] + pw[1] + pw[2] + pw[3] +
                             pw[4] + pw[5] + pw[6] + pw[7]);

        float4 acc = make_float4(0.f, 0.f, 0.f, 0.f);
        #pragma unroll
        for (int j = 0; j < 8; j++) {
            acc.x += pw[j] * nv[j].x;  acc.y += pw[j] * nv[j].y;
            acc.z += pw[j] * nv[j].z;  acc.w += pw[j] * nv[j].w;
        }

        // iter-0 hop-1 aggregator input: self(e1g) + weighted neighbors
        float4 in1 = make_float4(v1.x + acc.x * inv1, v1.y + acc.y * inv1,
                                 v1.z + acc.z * inv1, v1.w + acc.w * inv1);
        s_in1[wid][g * PITCH4 + q] = in1;
        __syncwarp();

        // matvec + sigmoid: lane computes group g, dims q*4..q*4+3
        float4 h1;
        {
            const float* ing = (const float*)&s_in1[wid][g * PITCH4];
            const float4* W4v = (const float4*)s_W;
            float4 o = s_b4[q];
            #pragma unroll
            for (int i = 0; i < 16; i++) {
                float xv = ing[i];
                float4 w = W4v[i * 4 + q];
                o.x += xv * w.x; o.y += xv * w.y;
                o.z += xv * w.z; o.w += xv * w.w;
            }
            h1 = make_float4(sigmoidf_(o.x), sigmoidf_(o.y),
                             sigmoidf_(o.z), sigmoidf_(o.w));
        }

        // ---- iter-0 hop-0: weighted sum over e1 rows (reduce over g) ----
        float pe0 = s_E[r0g];
        float cx = pe0 * v1.x, cy = pe0 * v1.y, cz = pe0 * v1.z, cw = pe0 * v1.w;
        float se = pe0;
        #pragma unroll
        for (int m = 4; m <= 16; m <<= 1) {
            cx += __shfl_xor_sync(FULL, cx, m);
            cy += __shfl_xor_sync(FULL, cy, m);
            cz += __shfl_xor_sync(FULL, cz, m);
            cw += __shfl_xor_sync(FULL, cw, m);
            se += __shfl_xor_sync(FULL, se, m);
        }
        const float inv0 = 1.0f / se;
        float4 in0 = make_float4(e0row.x + cx * inv0, e0row.y + cy * inv0,
                                 e0row.z + cz * inv0, e0row.w + cw * inv0);
        if (g == 0) s_in0[wid][q] = in0;
        __syncwarp();

        float4 h0;
        {
            const float* ing = (const float*)s_in0[wid];
            const float4* W4v = (const float4*)s_W;
            float4 o = s_b4[q];
            #pragma unroll
            for (int i = 0; i < 16; i++) {
                float xv = ing[i];
                float4 w = W4v[i * 4 + q];
                o.x += xv * w.x; o.y += xv * w.y;
                o.z += xv * w.z; o.w += xv * w.w;
            }
            h0 = make_float4(sigmoidf_(o.x), sigmoidf_(o.y),
                             sigmoidf_(o.z), sigmoidf_(o.w));
        }
        __syncwarp();

        // ---- iter-1 hop-0: neighbors are h1 vectors, weights p0 reused ----
        cx = pe0 * h1.x; cy = pe0 * h1.y; cz = pe0 * h1.z; cw = pe0 * h1.w;
        #pragma unroll
        for (int m = 4; m <= 16; m <<= 1) {
            cx += __shfl_xor_sync(FULL, cx, m);
            cy += __shfl_xor_sync(FULL, cy, m);
            cz += __shfl_xor_sync(FULL, cz, m);
            cw += __shfl_xor_sync(FULL, cw, m);
        }
        float4 in2 = make_float4(h0.x + cx * inv0, h0.y + cy * inv0,
                                 h0.z + cz * inv0, h0.w + cw * inv0);
        if (g == 0) s_in0[wid][q] = in2;
        __syncwarp();

        {
            const float* ing = (const float*)s_in0[wid];
            const float4* W4v = (const float4*)s_W;
            float4 o = s_b4[q];
            #pragma unroll
            for (int i = 0; i < 16; i++) {
                float xv = ing[i];
                float4 w = W4v[i * 4 + q];
                o.x += xv * w.x; o.y += xv * w.y;
                o.z += xv * w.z; o.w += xv * w.w;
            }
            o = make_float4(fmaxf(tanhf(o.x), 0.f), fmaxf(tanhf(o.y), 0.f),
                            fmaxf(tanhf(o.z), 0.f), fmaxf(tanhf(o.w), 0.f));
            acc_sum.x += o.x; acc_sum.y += o.y;
            acc_sum.z += o.z; acc_sum.w += o.w;
            acc_max.x = fmaxf(acc_max.x, o.x);
            acc_max.y = fmaxf(acc_max.y, o.y);
            acc_max.z = fmaxf(acc_max.z, o.z);
            acc_max.w = fmaxf(acc_max.w, o.w);
        }
        __syncwarp();
    }

    if (g == 0) {
        s_psum[wid][q] = acc_sum;
        s_pmax[wid][q] = acc_max;
    }
    __syncthreads();

    // pooling across warps -> fusion[32]
    if (tid < 16) {
        float ssum = 0.0f, smax = 0.0f;
        #pragma unroll
        for (int w = 0; w < 16; w++) {
            ssum += ((const float*)s_psum[w])[tid];
            smax = fmaxf(smax, ((const float*)s_pmax[w])[tid]);
        }
        s_fusion[tid]      = ssum;
        s_fusion[16 + tid] = smax;
    }
    __syncthreads();

    // fc1: 32 -> 64, relu
    if (tid < 64) {
        float o = fc1_b[tid];
        #pragma unroll
        for (int i = 0; i < 32; i++) o += s_fusion[i] * fc1_W[i * 64 + tid];
        s_fc[tid] = fmaxf(o, 0.0f);
    }
    __syncthreads();

    // fc2: 64 -> 16, relu; dot with ent_emb[v]
    if (tid < 16) {
        float o = fc2_b[tid];
        #pragma unroll
        for (int i = 0; i < 64; i++) o += s_fc[i] * fc2_W[i * 16 + tid];
        o = fmaxf(o, 0.0f);
        s_dot[tid] = o * ent_emb[v[b] * D_ + tid];
    }
    __syncthreads();

    if (tid == 0) {
        float d = 0.0f;
        #pragma unroll
        for (int i = 0; i < 16; i++) d += s_dot[i];
        out[b * 17] = sigmoidf_(d);
    }
}

// ---------------------------------------------------------------------------
extern "C" void kernel_launch(void* const* d_in, const int* in_sizes, int n_in,
                              void* d_out, int out_size) {
    const float* usr_emb = (const float*)d_in[0];
    const float* ent_emb = (const float*)d_in[1];
    const float* rel_emb = (const float*)d_in[2];
    const float* agg_W   = (const float*)d_in[3];
    const float* agg_b   = (const float*)d_in[4];
    const float* fc1_W   = (const float*)d_in[5];
    const float* fc1_b   = (const float*)d_in[6];
    const float* fc2_W   = (const float*)d_in[7];
    const float* fc2_b   = (const float*)d_in[8];
    const float* mlp_W1  = (const float*)d_in[9];
    const float* mlp_b1  = (const float*)d_in[10];
    const float* mlp_W2  = (const float*)d_in[11];
    const float* mlp_b2  = (const float*)d_in[12];
    const float* mlp_W3  = (const float*)d_in[13];
    const float* mlp_b3  = (const float*)d_in[14];
    const float* mlp_W4  = (const float*)d_in[15];
    const float* mlp_b4  = (const float*)d_in[16];
    const float* se1     = (const float*)d_in[17];
    const float* se2     = (const float*)d_in[18];
    const float* se3     = (const float*)d_in[19];
    const float* noise_e = (const float*)d_in[20];
    const int*   u       = (const int*)d_in[21];
    const int*   v       = (const int*)d_in[22];
    const int*   click   = (const int*)d_in[23];
    const int*   adj_ent = (const int*)d_in[24];
    const int*   adj_rel = (const int*)d_in[25];
    const int*   t       = (const int*)d_in[26];
    float* out = (float*)d_out;

    alpha_kernel<<<1, 128>>>();

    diff_kernel<<<B_ / 2, 128>>>(usr_emb, noise_e, u, t,
                                 mlp_W1, mlp_b1, mlp_W2, mlp_b2,
                                 mlp_W3, mlp_b3, mlp_W4, mlp_b4,
                                 se1, se2, se3, out);

    kgcn_kernel<<<B_, 512>>>(ent_emb, rel_emb, usr_emb,
                             agg_W, agg_b, fc1_W, fc1_b, fc2_W, fc2_b,
                             u, v, click, adj_ent, adj_rel, out);
}

// round 6
// speedup vs baseline: 1.8677x; 1.2351x over previous
#include <cuda_runtime.h>
#include <cuda_bf16.h>

#define B_   512
#define S_   64
#define K_   8
#define D_   16
#define NSTEPS_ 100

#define FULL 0xffffffffu
#define PITCH4 5   // float4 pitch per group: conflict-free LDS in matvec

__device__ __forceinline__ float sigmoidf_(float x) {
    return 1.0f / (1.0f + __expf(-x));
}

// partial pooling scratch: [b][sc][ {sum,max} ][16]
__device__ float g_part[B_ * 4 * 32];

// ---------------------------------------------------------------------------
// Kernel 1: KGCN gather + aggregate. 2048 blocks = (b, s-chunk), 128 threads.
// Each of 4 warps handles 4 sequence positions. Lane = (g, q): g = hop-1
// group 0..7, q = float4 chunk 0..3 of the 16-dim embedding.
// ---------------------------------------------------------------------------
__global__ __launch_bounds__(128) void kgcn_gather(
    const float* __restrict__ ent_emb, const float* __restrict__ rel_emb,
    const float* __restrict__ usr_emb,
    const float* __restrict__ agg_W, const float* __restrict__ agg_b,
    const int* __restrict__ u, const int* __restrict__ click_seq,
    const int* __restrict__ adj_ent, const int* __restrict__ adj_rel)
{
    __shared__ float  s_user[16];
    __shared__ float  s_E[64];                 // exp(user.rel[r]/16)
    __shared__ float  s_W[256];
    __shared__ float4 s_b4[4];
    __shared__ int    s_click[16];
    __shared__ float4 s_in1[4][8 * PITCH4];
    __shared__ float4 s_in0[4][4];
    __shared__ float4 s_psum[4][4];
    __shared__ float4 s_pmax[4][4];

    const int blk  = blockIdx.x;
    const int b    = blk >> 2;
    const int sc   = blk & 3;
    const int tid  = threadIdx.x;
    const int wid  = tid >> 5;
    const int lane = tid & 31;
    const int g    = lane >> 2;
    const int q    = lane & 3;

    // ---- preamble ----
    if (tid < 16) s_user[tid] = usr_emb[u[b] * D_ + tid];
    if (tid >= 16 && tid < 32) s_click[tid - 16] = click_seq[b * S_ + sc * 16 + (tid - 16)];
    s_W[tid]       = agg_W[tid];
    s_W[tid + 128] = agg_W[tid + 128];
    if (tid >= 32 && tid < 36) {
        int c = tid - 32;
        s_b4[c] = make_float4(agg_b[c * 4], agg_b[c * 4 + 1],
                              agg_b[c * 4 + 2], agg_b[c * 4 + 3]);
    }
    __syncthreads();

    if (tid < 64) {
        const float4* rel4 = reinterpret_cast<const float4*>(rel_emb);
        const float4* us4  = reinterpret_cast<const float4*>(s_user);
        float sum = 0.0f;
        #pragma unroll
        for (int c = 0; c < 4; c++) {
            float4 r = rel4[tid * 4 + c];
            float4 uu = us4[c];
            sum += r.x * uu.x + r.y * uu.y + r.z * uu.z + r.w * uu.w;
        }
        s_E[tid] = __expf(sum * 0.0625f);   // scores tiny; no max-shift needed
    }
    __syncthreads();

    const float4* ent4  = reinterpret_cast<const float4*>(ent_emb);
    const int4*   adjE4 = reinterpret_cast<const int4*>(adj_ent);
    const int4*   adjR4 = reinterpret_cast<const int4*>(adj_rel);

    // ---- hoist all per-iteration indices ----
    int e0s[4], e1s[4], r0s[4];
    #pragma unroll
    for (int it = 0; it < 4; it++) e0s[it] = s_click[wid * 4 + it];
    #pragma unroll
    for (int it = 0; it < 4; it++) {
        e1s[it] = adj_ent[e0s[it] * K_ + g];
        r0s[it] = adj_rel[e0s[it] * K_ + g];
    }

    // prefetch iteration 0
    int4   neb0 = adjE4[e1s[0] * 2],     neb1 = adjE4[e1s[0] * 2 + 1];
    int4   nrb0 = adjR4[e1s[0] * 2],     nrb1 = adjR4[e1s[0] * 2 + 1];
    float4 nv1  = ent4[e1s[0] * 4 + q];
    float4 ne0  = ent4[e0s[0] * 4 + q];

    float4 acc_sum = make_float4(0.f, 0.f, 0.f, 0.f);
    float4 acc_max = make_float4(0.f, 0.f, 0.f, 0.f);

    #pragma unroll
    for (int it = 0; it < 4; ++it) {
        const int4   eb0 = neb0, eb1 = neb1, rb0 = nrb0, rb1 = nrb1;
        const float4 v1 = nv1, e0row = ne0;

        // issue hop-2 gathers first (MLP=8)
        int ei[8] = {eb0.x, eb0.y, eb0.z, eb0.w, eb1.x, eb1.y, eb1.z, eb1.w};
        float4 nv[8];
        #pragma unroll
        for (int j = 0; j < 8; j++) nv[j] = ent4[ei[j] * 4 + q];

        // prefetch next iteration's rows while nv is in flight
        if (it < 3) {
            neb0 = adjE4[e1s[it + 1] * 2];
            neb1 = adjE4[e1s[it + 1] * 2 + 1];
            nrb0 = adjR4[e1s[it + 1] * 2];
            nrb1 = adjR4[e1s[it + 1] * 2 + 1];
            nv1  = ent4[e1s[it + 1] * 4 + q];
            ne0  = ent4[e0s[it + 1] * 4 + q];
        }

        // softmax weights for group g
        float pw[8];
        pw[0] = s_E[rb0.x]; pw[1] = s_E[rb0.y]; pw[2] = s_E[rb0.z]; pw[3] = s_E[rb0.w];
        pw[4] = s_E[rb1.x]; pw[5] = s_E[rb1.y]; pw[6] = s_E[rb1.z]; pw[7] = s_E[rb1.w];
        float inv1 = 1.0f / (pw[0] + pw[1] + pw[2] + pw[3] +
                             pw[4] + pw[5] + pw[6] + pw[7]);

        float4 acc = make_float4(0.f, 0.f, 0.f, 0.f);
        #pragma unroll
        for (int j = 0; j < 8; j++) {
            acc.x += pw[j] * nv[j].x;  acc.y += pw[j] * nv[j].y;
            acc.z += pw[j] * nv[j].z;  acc.w += pw[j] * nv[j].w;
        }

        // iter-0 hop-1 aggregator input
        float4 in1 = make_float4(v1.x + acc.x * inv1, v1.y + acc.y * inv1,
                                 v1.z + acc.z * inv1, v1.w + acc.w * inv1);
        s_in1[wid][g * PITCH4 + q] = in1;
        __syncwarp();

        float4 h1;
        {
            const float* ing = (const float*)&s_in1[wid][g * PITCH4];
            const float4* W4v = (const float4*)s_W;
            float4 o = s_b4[q];
            #pragma unroll
            for (int i = 0; i < 16; i++) {
                float xv = ing[i];
                float4 w = W4v[i * 4 + q];
                o.x += xv * w.x; o.y += xv * w.y;
                o.z += xv * w.z; o.w += xv * w.w;
            }
            h1 = make_float4(sigmoidf_(o.x), sigmoidf_(o.y),
                             sigmoidf_(o.z), sigmoidf_(o.w));
        }

        // ---- iter-0 hop-0: weighted sum over e1 rows (reduce over g) ----
        const float pe0 = s_E[r0s[it]];
        float cx = pe0 * v1.x, cy = pe0 * v1.y, cz = pe0 * v1.z, cw = pe0 * v1.w;
        float se = pe0;
        #pragma unroll
        for (int m = 4; m <= 16; m <<= 1) {
            cx += __shfl_xor_sync(FULL, cx, m);
            cy += __shfl_xor_sync(FULL, cy, m);
            cz += __shfl_xor_sync(FULL, cz, m);
            cw += __shfl_xor_sync(FULL, cw, m);
            se += __shfl_xor_sync(FULL, se, m);
        }
        const float inv0 = 1.0f / se;
        if (g == 0)
            s_in0[wid][q] = make_float4(e0row.x + cx * inv0, e0row.y + cy * inv0,
                                        e0row.z + cz * inv0, e0row.w + cw * inv0);
        __syncwarp();

        float4 h0;
        {
            const float* ing = (const float*)s_in0[wid];
            const float4* W4v = (const float4*)s_W;
            float4 o = s_b4[q];
            #pragma unroll
            for (int i = 0; i < 16; i++) {
                float xv = ing[i];
                float4 w = W4v[i * 4 + q];
                o.x += xv * w.x; o.y += xv * w.y;
                o.z += xv * w.z; o.w += xv * w.w;
            }
            h0 = make_float4(sigmoidf_(o.x), sigmoidf_(o.y),
                             sigmoidf_(o.z), sigmoidf_(o.w));
        }
        __syncwarp();

        // ---- iter-1 hop-0: neighbors = h1, weights p0 reused ----
        cx = pe0 * h1.x; cy = pe0 * h1.y; cz = pe0 * h1.z; cw = pe0 * h1.w;
        #pragma unroll
        for (int m = 4; m <= 16; m <<= 1) {
            cx += __shfl_xor_sync(FULL, cx, m);
            cy += __shfl_xor_sync(FULL, cy, m);
            cz += __shfl_xor_sync(FULL, cz, m);
            cw += __shfl_xor_sync(FULL, cw, m);
        }
        if (g == 0)
            s_in0[wid][q] = make_float4(h0.x + cx * inv0, h0.y + cy * inv0,
                                        h0.z + cz * inv0, h0.w + cw * inv0);
        __syncwarp();

        {
            const float* ing = (const float*)s_in0[wid];
            const float4* W4v = (const float4*)s_W;
            float4 o = s_b4[q];
            #pragma unroll
            for (int i = 0; i < 16; i++) {
                float xv = ing[i];
                float4 w = W4v[i * 4 + q];
                o.x += xv * w.x; o.y += xv * w.y;
                o.z += xv * w.z; o.w += xv * w.w;
            }
            o = make_float4(fmaxf(tanhf(o.x), 0.f), fmaxf(tanhf(o.y), 0.f),
                            fmaxf(tanhf(o.z), 0.f), fmaxf(tanhf(o.w), 0.f));
            acc_sum.x += o.x; acc_sum.y += o.y;
            acc_sum.z += o.z; acc_sum.w += o.w;
            acc_max.x = fmaxf(acc_max.x, o.x);
            acc_max.y = fmaxf(acc_max.y, o.y);
            acc_max.z = fmaxf(acc_max.z, o.z);
            acc_max.w = fmaxf(acc_max.w, o.w);
        }
        __syncwarp();
    }

    if (g == 0) {
        s_psum[wid][q] = acc_sum;
        s_pmax[wid][q] = acc_max;
    }
    __syncthreads();

    if (tid < 16) {
        float ss = 0.0f, mm = 0.0f;
        #pragma unroll
        for (int w = 0; w < 4; w++) {
            ss += ((const float*)s_psum[w])[tid];
            mm = fmaxf(mm, ((const float*)s_pmax[w])[tid]);
        }
        const int base = (b * 4 + sc) * 32;
        g_part[base + tid]      = ss;
        g_part[base + 16 + tid] = mm;
    }
}

// ---------------------------------------------------------------------------
// Kernel 2: finish. One block per batch element, 128 threads.
// Pools partials -> FC head -> out[b*17], plus the full diffusion MLP
// (alpha schedule computed in-block via masked log-sum) -> out[b*17+1..16].
// ---------------------------------------------------------------------------
__global__ __launch_bounds__(128) void finish_kernel(
    const float* __restrict__ ent_emb, const float* __restrict__ usr_emb,
    const float* __restrict__ noise,
    const int* __restrict__ u, const int* __restrict__ v,
    const int* __restrict__ t,
    const float* __restrict__ fc1_W, const float* __restrict__ fc1_b,
    const float* __restrict__ fc2_W, const float* __restrict__ fc2_b,
    const float* __restrict__ W1, const float* __restrict__ b1,
    const float* __restrict__ W2, const float* __restrict__ b2,
    const float* __restrict__ W3, const float* __restrict__ b3,
    const float* __restrict__ W4, const float* __restrict__ b4,
    const float* __restrict__ se1, const float* __restrict__ se2,
    const float* __restrict__ se3,
    float* __restrict__ out)
{
    __shared__ float s_fusion[32];
    __shared__ float s_fc[64];
    __shared__ float s_dot[16];
    __shared__ float s_xs[16];
    __shared__ float s_bufA[128];
    __shared__ float s_bufB[128];
    __shared__ float s_saso[2];

    const int b   = blockIdx.x;
    const int tid = threadIdx.x;
    const int tv  = t[b];

    // warp 0: alpha schedule via masked log-sum over the 100 beta terms
    if (tid < 32) {
        float lsum = 0.0f;
        for (int i = tid; i < NSTEPS_; i += 32) {
            if (i <= tv) {
                float z    = -6.0f + 12.0f * (float)i / 99.0f;
                float sig  = 1.0f / (1.0f + expf(-z));
                float beta = sig * (0.005f - 1e-5f) + 1e-5f;
                lsum += log1pf(-beta);
            }
        }
        #pragma unroll
        for (int m = 16; m >= 1; m >>= 1) lsum += __shfl_xor_sync(FULL, lsum, m);
        if (tid == 0) {
            float prod = expf(lsum);
            s_saso[0] = sqrtf(prod);
            s_saso[1] = sqrtf(1.0f - prod);
        }
    }

    // warp 1: pooled fusion from scratch partials
    if (tid >= 32 && tid < 48) {
        const int d = tid - 32;
        float ss = 0.0f, mm = 0.0f;
        #pragma unroll
        for (int sc = 0; sc < 4; sc++) {
            const int base = (b * 4 + sc) * 32;
            ss += g_part[base + d];
            mm = fmaxf(mm, g_part[base + 16 + d]);
        }
        s_fusion[d]      = ss;    // relu no-op: nonneg
        s_fusion[16 + d] = mm;
    }
    __syncthreads();

    // xs for diffusion; fc1 for head (disjoint threads)
    if (tid < 16)
        s_xs[tid] = usr_emb[u[b] * D_ + tid] * s_saso[0] + noise[b * D_ + tid] * s_saso[1];
    if (tid >= 64) {
        const int o_ = tid - 64;
        float acc = fc1_b[o_];
        #pragma unroll
        for (int i = 0; i < 32; i++) acc += s_fusion[i] * fc1_W[i * 64 + o_];
        s_fc[o_] = fmaxf(acc, 0.0f);
    }
    __syncthreads();

    // diffusion layer 1 (all threads) + fc2/dot (tid<16)
    {
        float a = b1[tid];
        #pragma unroll
        for (int i = 0; i < 16; i++) a += s_xs[i] * W1[i * 128 + tid];
        s_bufA[tid] = fmaxf(a + se1[tv * 128 + tid], 0.0f);
    }
    if (tid < 16) {
        float o_ = fc2_b[tid];
        #pragma unroll
        for (int i = 0; i < 64; i++) o_ += s_fc[i] * fc2_W[i * 16 + tid];
        o_ = fmaxf(o_, 0.0f);
        s_dot[tid] = o_ * ent_emb[v[b] * D_ + tid];
    }
    __syncthreads();

    // diffusion layer 2 + final sigmoid dot (tid 0)
    {
        float a = b2[tid];
        #pragma unroll 8
        for (int i = 0; i < 128; i++) a += s_bufA[i] * W2[i * 128 + tid];
        s_bufB[tid] = fmaxf(a + se2[tv * 128 + tid], 0.0f);
    }
    if (tid == 0) {
        float d = 0.0f;
        #pragma unroll
        for (int i = 0; i < 16; i++) d += s_dot[i];
        out[b * 17] = sigmoidf_(d);
    }
    __syncthreads();

    // diffusion layer 3
    {
        float a = b3[tid];
        #pragma unroll 8
        for (int i = 0; i < 128; i++) a += s_bufB[i] * W3[i * 128 + tid];
        s_bufA[tid] = fmaxf(a + se3[tv * 128 + tid], 0.0f);
    }
    __syncthreads();

    // diffusion layer 4 (128 -> 16)
    if (tid < 16) {
        float o_ = b4[tid];
        #pragma unroll 8
        for (int i = 0; i < 128; i++) o_ += s_bufA[i] * W4[i * 16 + tid];
        out[b * 17 + 1 + tid] = o_;
    }
}

// ---------------------------------------------------------------------------
extern "C" void kernel_launch(void* const* d_in, const int* in_sizes, int n_in,
                              void* d_out, int out_size) {
    const float* usr_emb = (const float*)d_in[0];
    const float* ent_emb = (const float*)d_in[1];
    const float* rel_emb = (const float*)d_in[2];
    const float* agg_W   = (const float*)d_in[3];
    const float* agg_b   = (const float*)d_in[4];
    const float* fc1_W   = (const float*)d_in[5];
    const float* fc1_b   = (const float*)d_in[6];
    const float* fc2_W   = (const float*)d_in[7];
    const float* fc2_b   = (const float*)d_in[8];
    const float* mlp_W1  = (const float*)d_in[9];
    const float* mlp_b1  = (const float*)d_in[10];
    const float* mlp_W2  = (const float*)d_in[11];
    const float* mlp_b2  = (const float*)d_in[12];
    const float* mlp_W3  = (const float*)d_in[13];
    const float* mlp_b3  = (const float*)d_in[14];
    const float* mlp_W4  = (const float*)d_in[15];
    const float* mlp_b4  = (const float*)d_in[16];
    const float* se1     = (const float*)d_in[17];
    const float* se2     = (const float*)d_in[18];
    const float* se3     = (const float*)d_in[19];
    const float* noise_e = (const float*)d_in[20];
    const int*   u       = (const int*)d_in[21];
    const int*   v       = (const int*)d_in[22];
    const int*   click   = (const int*)d_in[23];
    const int*   adj_ent = (const int*)d_in[24];
    const int*   adj_rel = (const int*)d_in[25];
    const int*   t       = (const int*)d_in[26];
    float* out = (float*)d_out;

    kgcn_gather<<<B_ * 4, 128>>>(ent_emb, rel_emb, usr_emb, agg_W, agg_b,
                                 u, click, adj_ent, adj_rel);

    finish_kernel<<<B_, 128>>>(ent_emb, usr_emb, noise_e, u, v, t,
                               fc1_W, fc1_b, fc2_W, fc2_b,
                               mlp_W1, mlp_b1, mlp_W2, mlp_b2,
                               mlp_W3, mlp_b3, mlp_W4, mlp_b4,
                               se1, se2, se3, out);
}

// round 7
// speedup vs baseline: 2.3612x; 1.2642x over previous
#include <cuda_runtime.h>
#include <cuda_bf16.h>

#define B_   512
#define S_   64
#define K_   8
#define D_   16
#define NSTEPS_ 100

#define FULL 0xffffffffu
#define PITCH4 5   // float4 pitch per group: conflict-free LDS in matvec

__device__ __forceinline__ float sigmoidf_(float x) {
    return 1.0f / (1.0f + __expf(-x));
}

// partial pooling scratch: [b][sc][ {sum,max} ][16]
__device__ float g_part[B_ * 4 * 32];

// ---------------------------------------------------------------------------
// Kernel 1: KGCN gather + aggregate. 2048 blocks = (b, s-chunk), 128 threads.
// Each of 4 warps handles 4 sequence positions. Lane = (g, q): g = hop-1
// group 0..7, q = float4 chunk 0..3 of the 16-dim embedding.
// ---------------------------------------------------------------------------
__global__ __launch_bounds__(128) void kgcn_gather(
    const float* __restrict__ ent_emb, const float* __restrict__ rel_emb,
    const float* __restrict__ usr_emb,
    const float* __restrict__ agg_W, const float* __restrict__ agg_b,
    const int* __restrict__ u, const int* __restrict__ click_seq,
    const int* __restrict__ adj_ent, const int* __restrict__ adj_rel)
{
    __shared__ float  s_E[64];                 // exp(user.rel[r]/16)
    __shared__ float  s_W[256];
    __shared__ float4 s_b4[4];
    __shared__ float4 s_in1[4][8 * PITCH4];
    __shared__ float4 s_in0[4][4];
    __shared__ float4 s_psum[4][4];
    __shared__ float4 s_pmax[4][4];

    const int blk  = blockIdx.x;
    const int b    = blk >> 2;
    const int sc   = blk & 3;
    const int tid  = threadIdx.x;
    const int wid  = tid >> 5;
    const int lane = tid & 31;
    const int g    = lane >> 2;
    const int q    = lane & 3;

    // ---- issue the index chain FIRST so it overlaps the preamble ----
    int e0s[4], e1s[4], r0s[4];
    #pragma unroll
    for (int it = 0; it < 4; it++)
        e0s[it] = click_seq[b * S_ + sc * 16 + wid * 4 + it];
    #pragma unroll
    for (int it = 0; it < 4; it++) {
        e1s[it] = adj_ent[e0s[it] * K_ + g];
        r0s[it] = adj_rel[e0s[it] * K_ + g];
    }

    // ---- preamble (overlaps index-chain latency) ----
    s_W[tid]       = agg_W[tid];
    s_W[tid + 128] = agg_W[tid + 128];
    if (tid >= 64 && tid < 68) {
        int c = tid - 64;
        s_b4[c] = make_float4(agg_b[c * 4], agg_b[c * 4 + 1],
                              agg_b[c * 4 + 2], agg_b[c * 4 + 3]);
    }
    if (tid < 64) {
        const float4* us4  = reinterpret_cast<const float4*>(usr_emb) + (size_t)u[b] * 4;
        const float4* rel4 = reinterpret_cast<const float4*>(rel_emb) + tid * 4;
        float sum = 0.0f;
        #pragma unroll
        for (int c = 0; c < 4; c++) {
            float4 r = rel4[c];
            float4 uu = us4[c];
            sum += r.x * uu.x + r.y * uu.y + r.z * uu.z + r.w * uu.w;
        }
        s_E[tid] = __expf(sum * 0.0625f);   // scores tiny; no max-shift needed
    }
    __syncthreads();

    const float4* ent4  = reinterpret_cast<const float4*>(ent_emb);
    const int4*   adjE4 = reinterpret_cast<const int4*>(adj_ent);
    const int4*   adjR4 = reinterpret_cast<const int4*>(adj_rel);
    const float4* W4v   = reinterpret_cast<const float4*>(s_W);

    // prefetch iteration 0
    int4   neb0 = adjE4[e1s[0] * 2],     neb1 = adjE4[e1s[0] * 2 + 1];
    int4   nrb0 = adjR4[e1s[0] * 2],     nrb1 = adjR4[e1s[0] * 2 + 1];
    float4 nv1  = ent4[e1s[0] * 4 + q];
    float4 ne0  = ent4[e0s[0] * 4 + q];

    float4 acc_sum = make_float4(0.f, 0.f, 0.f, 0.f);
    float4 acc_max = make_float4(0.f, 0.f, 0.f, 0.f);

    #pragma unroll
    for (int it = 0; it < 4; ++it) {
        const int4   eb0 = neb0, eb1 = neb1, rb0 = nrb0, rb1 = nrb1;
        const float4 v1 = nv1, e0row = ne0;

        // issue hop-2 gathers first (MLP=8)
        int ei[8] = {eb0.x, eb0.y, eb0.z, eb0.w, eb1.x, eb1.y, eb1.z, eb1.w};
        float4 nv[8];
        #pragma unroll
        for (int j = 0; j < 8; j++) nv[j] = ent4[ei[j] * 4 + q];

        // prefetch next iteration's rows while nv is in flight
        if (it < 3) {
            neb0 = adjE4[e1s[it + 1] * 2];
            neb1 = adjE4[e1s[it + 1] * 2 + 1];
            nrb0 = adjR4[e1s[it + 1] * 2];
            nrb1 = adjR4[e1s[it + 1] * 2 + 1];
            nv1  = ent4[e1s[it + 1] * 4 + q];
            ne0  = ent4[e0s[it + 1] * 4 + q];
        }

        // softmax weights for group g
        float pw[8];
        pw[0] = s_E[rb0.x]; pw[1] = s_E[rb0.y]; pw[2] = s_E[rb0.z]; pw[3] = s_E[rb0.w];
        pw[4] = s_E[rb1.x]; pw[5] = s_E[rb1.y]; pw[6] = s_E[rb1.z]; pw[7] = s_E[rb1.w];
        float inv1 = 1.0f / (pw[0] + pw[1] + pw[2] + pw[3] +
                             pw[4] + pw[5] + pw[6] + pw[7]);

        float4 acc = make_float4(0.f, 0.f, 0.f, 0.f);
        #pragma unroll
        for (int j = 0; j < 8; j++) {
            acc.x += pw[j] * nv[j].x;  acc.y += pw[j] * nv[j].y;
            acc.z += pw[j] * nv[j].z;  acc.w += pw[j] * nv[j].w;
        }

        // iter-0 hop-1 aggregator input (distinct per g -> full-warp matvec)
        float4 in1 = make_float4(v1.x + acc.x * inv1, v1.y + acc.y * inv1,
                                 v1.z + acc.z * inv1, v1.w + acc.w * inv1);
        s_in1[wid][g * PITCH4 + q] = in1;
        __syncwarp();

        float4 h1;
        {
            const float* ing = (const float*)&s_in1[wid][g * PITCH4];
            float4 o = s_b4[q];
            #pragma unroll
            for (int i = 0; i < 16; i++) {
                float xv = ing[i];
                float4 w = W4v[i * 4 + q];
                o.x += xv * w.x; o.y += xv * w.y;
                o.z += xv * w.z; o.w += xv * w.w;
            }
            h1 = make_float4(sigmoidf_(o.x), sigmoidf_(o.y),
                             sigmoidf_(o.z), sigmoidf_(o.w));
        }

        // ---- iter-0 hop-0: weighted sum over e1 rows (reduce over g) ----
        const float pe0 = s_E[r0s[it]];
        float cx = pe0 * v1.x, cy = pe0 * v1.y, cz = pe0 * v1.z, cw = pe0 * v1.w;
        float se = pe0;
        #pragma unroll
        for (int m = 4; m <= 16; m <<= 1) {
            cx += __shfl_xor_sync(FULL, cx, m);
            cy += __shfl_xor_sync(FULL, cy, m);
            cz += __shfl_xor_sync(FULL, cz, m);
            cw += __shfl_xor_sync(FULL, cw, m);
            se += __shfl_xor_sync(FULL, se, m);
        }
        const float inv0 = 1.0f / se;
        if (g == 0)
            s_in0[wid][q] = make_float4(e0row.x + cx * inv0, e0row.y + cy * inv0,
                                        e0row.z + cz * inv0, e0row.w + cw * inv0);
        __syncwarp();

        // h0 matvec, i split across g (2 i's per lane) + butterfly reduce
        float4 h0;
        {
            const float* in0f = (const float*)s_in0[wid];
            float x0 = in0f[2 * g], x1 = in0f[2 * g + 1];
            float4 w0 = W4v[(2 * g) * 4 + q];
            float4 w1 = W4v[(2 * g + 1) * 4 + q];
            float ox = x0 * w0.x + x1 * w1.x;
            float oy = x0 * w0.y + x1 * w1.y;
            float oz = x0 * w0.z + x1 * w1.z;
            float ow = x0 * w0.w + x1 * w1.w;
            #pragma unroll
            for (int m = 4; m <= 16; m <<= 1) {
                ox += __shfl_xor_sync(FULL, ox, m);
                oy += __shfl_xor_sync(FULL, oy, m);
                oz += __shfl_xor_sync(FULL, oz, m);
                ow += __shfl_xor_sync(FULL, ow, m);
            }
            float4 bb = s_b4[q];
            h0 = make_float4(sigmoidf_(ox + bb.x), sigmoidf_(oy + bb.y),
                             sigmoidf_(oz + bb.z), sigmoidf_(ow + bb.w));
        }

        // ---- iter-1 hop-0: neighbors = h1, weights p0 reused ----
        cx = pe0 * h1.x; cy = pe0 * h1.y; cz = pe0 * h1.z; cw = pe0 * h1.w;
        #pragma unroll
        for (int m = 4; m <= 16; m <<= 1) {
            cx += __shfl_xor_sync(FULL, cx, m);
            cy += __shfl_xor_sync(FULL, cy, m);
            cz += __shfl_xor_sync(FULL, cz, m);
            cw += __shfl_xor_sync(FULL, cw, m);
        }
        if (g == 0)
            s_in0[wid][q] = make_float4(h0.x + cx * inv0, h0.y + cy * inv0,
                                        h0.z + cz * inv0, h0.w + cw * inv0);
        __syncwarp();

        // final matvec, i split across g + butterfly reduce, tanh + relu
        {
            const float* in0f = (const float*)s_in0[wid];
            float x0 = in0f[2 * g], x1 = in0f[2 * g + 1];
            float4 w0 = W4v[(2 * g) * 4 + q];
            float4 w1 = W4v[(2 * g + 1) * 4 + q];
            float ox = x0 * w0.x + x1 * w1.x;
            float oy = x0 * w0.y + x1 * w1.y;
            float oz = x0 * w0.z + x1 * w1.z;
            float ow = x0 * w0.w + x1 * w1.w;
            #pragma unroll
            for (int m = 4; m <= 16; m <<= 1) {
                ox += __shfl_xor_sync(FULL, ox, m);
                oy += __shfl_xor_sync(FULL, oy, m);
                oz += __shfl_xor_sync(FULL, oz, m);
                ow += __shfl_xor_sync(FULL, ow, m);
            }
            float4 bb = s_b4[q];
            float fx = fmaxf(tanhf(ox + bb.x), 0.f);
            float fy = fmaxf(tanhf(oy + bb.y), 0.f);
            float fz = fmaxf(tanhf(oz + bb.z), 0.f);
            float fw = fmaxf(tanhf(ow + bb.w), 0.f);
            acc_sum.x += fx; acc_sum.y += fy;
            acc_sum.z += fz; acc_sum.w += fw;
            acc_max.x = fmaxf(acc_max.x, fx);
            acc_max.y = fmaxf(acc_max.y, fy);
            acc_max.z = fmaxf(acc_max.z, fz);
            acc_max.w = fmaxf(acc_max.w, fw);
        }
        __syncwarp();
    }

    if (g == 0) {
        s_psum[wid][q] = acc_sum;
        s_pmax[wid][q] = acc_max;
    }
    __syncthreads();

    if (tid < 16) {
        float ss = 0.0f, mm = 0.0f;
        #pragma unroll
        for (int w = 0; w < 4; w++) {
            ss += ((const float*)s_psum[w])[tid];
            mm = fmaxf(mm, ((const float*)s_pmax[w])[tid]);
        }
        const int base = (b * 4 + sc) * 32;
        g_part[base + tid]      = ss;
        g_part[base + 16 + tid] = mm;
    }
}

// ---------------------------------------------------------------------------
// Kernel 2: finish. One block per batch element, 512 threads.
// Diffusion MLP with i-parallel partial sums (4 threads per output for the
// 128-wide layers), head (fc1/fc2/dot) interleaved in the phase structure.
// ---------------------------------------------------------------------------
__global__ __launch_bounds__(512) void finish_kernel(
    const float* __restrict__ ent_emb, const float* __restrict__ usr_emb,
    const float* __restrict__ noise,
    const int* __restrict__ u, const int* __restrict__ v,
    const int* __restrict__ t,
    const float* __restrict__ fc1_W, const float* __restrict__ fc1_b,
    const float* __restrict__ fc2_W, const float* __restrict__ fc2_b,
    const float* __restrict__ W1, const float* __restrict__ b1,
    const float* __restrict__ W2, const float* __restrict__ b2,
    const float* __restrict__ W3, const float* __restrict__ b3,
    const float* __restrict__ W4, const float* __restrict__ b4,
    const float* __restrict__ se1, const float* __restrict__ se2,
    const float* __restrict__ se3,
    float* __restrict__ out)
{
    __shared__ float s_fusion[32];
    __shared__ float s_fc[64];
    __shared__ float s_dot[16];
    __shared__ float s_xs[16];
    __shared__ float s_bufA[128];
    __shared__ float s_bufB[128];
    __shared__ float s_part[512];
    __shared__ float s_saso[2];

    const int b   = blockIdx.x;
    const int tid = threadIdx.x;
    const int tv  = t[b];
    const int o   = tid & 127;   // output index for 128-wide layers
    const int c   = tid >> 7;    // i-quarter 0..3

    // ---- P0: alpha schedule (warp 0) + fusion pooling (warp 1) ----
    if (tid < 32) {
        float lsum = 0.0f;
        for (int i = tid; i < NSTEPS_; i += 32) {
            if (i <= tv) {
                float z    = -6.0f + 12.0f * (float)i / 99.0f;
                float sig  = 1.0f / (1.0f + expf(-z));
                float beta = sig * (0.005f - 1e-5f) + 1e-5f;
                lsum += log1pf(-beta);
            }
        }
        #pragma unroll
        for (int m = 16; m >= 1; m >>= 1) lsum += __shfl_xor_sync(FULL, lsum, m);
        if (tid == 0) {
            float prod = expf(lsum);
            s_saso[0] = sqrtf(prod);
            s_saso[1] = sqrtf(1.0f - prod);
        }
    }
    if (tid >= 32 && tid < 48) {
        const int d = tid - 32;
        float ss = 0.0f, mm = 0.0f;
        #pragma unroll
        for (int sc = 0; sc < 4; sc++) {
            const int base = (b * 4 + sc) * 32;
            ss += g_part[base + d];
            mm = fmaxf(mm, g_part[base + 16 + d]);
        }
        s_fusion[d]      = ss;
        s_fusion[16 + d] = mm;
    }
    __syncthreads();

    // ---- P1: xs (tid<16) + fc1 (tid 128..191) ----
    if (tid < 16)
        s_xs[tid] = usr_emb[u[b] * D_ + tid] * s_saso[0] + noise[b * D_ + tid] * s_saso[1];
    if (tid >= 128 && tid < 192) {
        const int oo = tid - 128;
        float a = fc1_b[oo];
        #pragma unroll
        for (int i = 0; i < 32; i++) a += s_fusion[i] * fc1_W[i * 64 + oo];
        s_fc[oo] = fmaxf(a, 0.0f);
    }
    __syncthreads();

    // ---- P2: diffusion L1 (tid<128) + fc2/dot-prep (tid 192..207) ----
    if (tid < 128) {
        float a = b1[tid] + se1[tv * 128 + tid];
        #pragma unroll
        for (int i = 0; i < 16; i++) a += s_xs[i] * W1[i * 128 + tid];
        s_bufA[tid] = fmaxf(a, 0.0f);
    }
    if (tid >= 192 && tid < 208) {
        const int oo = tid - 192;
        float a = fc2_b[oo];
        #pragma unroll 8
        for (int i = 0; i < 64; i++) a += s_fc[i] * fc2_W[i * 16 + oo];
        s_dot[oo] = fmaxf(a, 0.0f) * ent_emb[v[b] * D_ + oo];
    }
    __syncthreads();

    // ---- P3: L2 partials (all 512) ----
    float bias2 = 0.0f;
    if (c == 0) bias2 = b2[o] + se2[tv * 128 + o];   // prefetch for P4
    {
        float a = 0.0f;
        const int i0 = c * 32;
        #pragma unroll 8
        for (int i = 0; i < 32; i++) a += s_bufA[i0 + i] * W2[(i0 + i) * 128 + o];
        s_part[tid] = a;
    }
    __syncthreads();

    // ---- P4: combine L2 (tid<128) + final dot/out (tid==128) ----
    if (tid < 128) {
        float a = bias2 + s_part[o] + s_part[128 + o] + s_part[256 + o] + s_part[384 + o];
        s_bufB[o] = fmaxf(a, 0.0f);
    }
    if (tid == 128) {
        float d = 0.0f;
        #pragma unroll
        for (int i = 0; i < 16; i++) d += s_dot[i];
        out[b * 17] = sigmoidf_(d);
    }
    __syncthreads();

    // ---- P5: L3 partials (all 512) ----
    float bias3 = 0.0f;
    if (c == 0) bias3 = b3[o] + se3[tv * 128 + o];
    {
        float a = 0.0f;
        const int i0 = c * 32;
        #pragma unroll 8
        for (int i = 0; i < 32; i++) a += s_bufB[i0 + i] * W3[(i0 + i) * 128 + o];
        s_part[tid] = a;
    }
    __syncthreads();

    // ---- P6: combine L3 (tid<128) ----
    if (tid < 128) {
        float a = bias3 + s_part[o] + s_part[128 + o] + s_part[256 + o] + s_part[384 + o];
        s_bufA[o] = fmaxf(a, 0.0f);
    }
    __syncthreads();

    // ---- P7: L4 partials (tid<128): o4 = tid&15, c4 = tid>>4 (8 quarters) ----
    if (tid < 128) {
        const int o4 = tid & 15, c4 = tid >> 4;
        const int i0 = c4 * 16;
        float a = 0.0f;
        #pragma unroll
        for (int i = 0; i < 16; i++) a += s_bufA[i0 + i] * W4[(i0 + i) * 16 + o4];
        s_part[c4 * 16 + o4] = a;
    }
    __syncthreads();

    // ---- P8: combine L4 + write diff_out ----
    if (tid < 16) {
        float a = b4[tid];
        #pragma unroll
        for (int c4 = 0; c4 < 8; c4++) a += s_part[c4 * 16 + tid];
        out[b * 17 + 1 + tid] = a;
    }
}

// ---------------------------------------------------------------------------
extern "C" void kernel_launch(void* const* d_in, const int* in_sizes, int n_in,
                              void* d_out, int out_size) {
    const float* usr_emb = (const float*)d_in[0];
    const float* ent_emb = (const float*)d_in[1];
    const float* rel_emb = (const float*)d_in[2];
    const float* agg_W   = (const float*)d_in[3];
    const float* agg_b   = (const float*)d_in[4];
    const float* fc1_W   = (const float*)d_in[5];
    const float* fc1_b   = (const float*)d_in[6];
    const float* fc2_W   = (const float*)d_in[7];
    const float* fc2_b   = (const float*)d_in[8];
    const float* mlp_W1  = (const float*)d_in[9];
    const float* mlp_b1  = (const float*)d_in[10];
    const float* mlp_W2  = (const float*)d_in[11];
    const float* mlp_b2  = (const float*)d_in[12];
    const float* mlp_W3  = (const float*)d_in[13];
    const float* mlp_b3  = (const float*)d_in[14];
    const float* mlp_W4  = (const float*)d_in[15];
    const float* mlp_b4  = (const float*)d_in[16];
    const float* se1     = (const float*)d_in[17];
    const float* se2     = (const float*)d_in[18];
    const float* se3     = (const float*)d_in[19];
    const float* noise_e = (const float*)d_in[20];
    const int*   u       = (const int*)d_in[21];
    const int*   v       = (const int*)d_in[22];
    const int*   click   = (const int*)d_in[23];
    const int*   adj_ent = (const int*)d_in[24];
    const int*   adj_rel = (const int*)d_in[25];
    const int*   t       = (const int*)d_in[26];
    float* out = (float*)d_out;

    kgcn_gather<<<B_ * 4, 128>>>(ent_emb, rel_emb, usr_emb, agg_W, agg_b,
                                 u, click, adj_ent, adj_rel);

    finish_kernel<<<B_, 512>>>(ent_emb, usr_emb, noise_e, u, v, t,
                               fc1_W, fc1_b, fc2_W, fc2_b,
                               mlp_W1, mlp_b1, mlp_W2, mlp_b2,
                               mlp_W3, mlp_b3, mlp_W4, mlp_b4,
                               se1, se2, se3, out);
}